// round 11
// baseline (speedup 1.0000x reference)
#include <cuda_runtime.h>
#include <cuda_bf16.h>
#include <cstdint>

// Problem shapes (fixed for this dataset entry)
constexpr int B = 4;
constexpr int S = 4096;
constexpr int D = 2048;
constexpr int HALO  = 8;        // recurrence depth N_BLANKS
constexpr int NROWS = 2048;     // x values span [0, 2048)
constexpr int NTOK  = B * S;    // 16384 tokens
constexpr int TTW   = 64;       // weights-kernel t-tile
constexpr int SLOWG = 512;      // slow-path blocks in main kernel

// Device scratch (no allocs allowed)
__device__ float    g_w[NTOK * HALO];     // w_1..w_8 per token
__device__ unsigned g_flag[NTOK];         // nonzero-weight mask per token
__device__ int      g_off[NROWS + 1];     // row start offsets
__device__ int      g_cur[NROWS];         // scatter cursors
__device__ int      g_order[NTOK];        // token ids grouped by row

// ---------------------------------------------------------------------------
// K1: weight DP per t-tile.
//   w^k[t][j] = w^{k-1}[t][j] + p[t-k] * w^{k-1}[t-1][j-1],  w_0 == 1 implicit
//   p[t] = (x[t] >= 16) && (x[t+1] < 16), zero outside [0, S-1)
// ---------------------------------------------------------------------------
__global__ __launch_bounds__(128)
void weights_kernel(const int* __restrict__ x)
{
    const int b   = blockIdx.y;
    const int T0  = blockIdx.x * TTW;
    const int tid = threadIdx.x;

    __shared__ float sp[TTW + 2 * HALO];             // p[t], t = T0-2*HALO+i
    __shared__ float wbuf[2][TTW + HALO][HALO];

    for (int i = tid; i < TTW + 2 * HALO; i += 128) {
        int t = T0 - 2 * HALO + i;
        float pv = 0.0f;
        if (t >= 0 && t + 1 < S) {
            int xt  = x[b * S + t];
            int xt1 = x[b * S + t + 1];
            pv = (xt1 < 16 && xt >= 16) ? 1.0f : 0.0f;
        }
        sp[i] = pv;
    }
    float wloc[HALO];
#pragma unroll
    for (int j = 0; j < HALO; j++) wloc[j] = 0.0f;
    if (tid < TTW + HALO) {
#pragma unroll
        for (int j = 0; j < HALO; j++) wbuf[0][tid][j] = 0.0f;
    }
    __syncthreads();

    for (int k = 1; k <= HALO; k++) {
        const int cur = k & 1, prv = cur ^ 1;
        if (tid < TTW + HALO) {
            float nb[HALO - 1];
            float nb0 = 0.0f;
            if (tid > 0) {
                nb0 = 1.0f;
#pragma unroll
                for (int j = 0; j < HALO - 1; j++) nb[j] = wbuf[prv][tid - 1][j];
            } else {
#pragma unroll
                for (int j = 0; j < HALO - 1; j++) nb[j] = 0.0f;
            }
            const float pv = sp[tid + HALO - k];
            wloc[0] = fmaf(pv, nb0, wloc[0]);
#pragma unroll
            for (int j = 1; j < HALO; j++) wloc[j] = fmaf(pv, nb[j - 1], wloc[j]);
#pragma unroll
            for (int j = 0; j < HALO; j++) wbuf[cur][tid][j] = wloc[j];
        }
        __syncthreads();
    }

    if (tid >= HALO && tid < TTW + HALO) {
        const int t  = T0 - HALO + tid;              // in [T0, T0+TTW)
        const int tf = b * S + t;
        unsigned m = 0;
#pragma unroll
        for (int j = 0; j < HALO; j++) {
            if (wloc[j] != 0.0f) m |= (1u << (j + 1));
            g_w[(size_t)tf * HALO + j] = wloc[j];
        }
        g_flag[tf] = m;
    }
}

// ---------------------------------------------------------------------------
// K2: single-block histogram + exclusive scan -> g_off, g_cur
// ---------------------------------------------------------------------------
__global__ __launch_bounds__(1024)
void histprefix_kernel(const int* __restrict__ x)
{
    __shared__ int hist[NROWS];
    __shared__ int wsum[32];
    const int tid  = threadIdx.x;
    const int lane = tid & 31;
    const int wid  = tid >> 5;

    hist[tid] = 0;
    hist[tid + 1024] = 0;
    __syncthreads();

    for (int i = tid; i < NTOK; i += 1024)
        atomicAdd(&hist[x[i]], 1);
    __syncthreads();

    // scan of 2048 counts, 2 per thread
    const int a = hist[2 * tid];
    const int bb = hist[2 * tid + 1];
    const int s = a + bb;

    int incl = s;                                    // warp inclusive scan of s
#pragma unroll
    for (int off = 1; off < 32; off <<= 1) {
        const int n = __shfl_up_sync(0xFFFFFFFFu, incl, off);
        if (lane >= off) incl += n;
    }
    if (lane == 31) wsum[wid] = incl;
    __syncthreads();
    if (wid == 0) {
        const int ws = wsum[lane];
        int wincl = ws;
#pragma unroll
        for (int off = 1; off < 32; off <<= 1) {
            const int n = __shfl_up_sync(0xFFFFFFFFu, wincl, off);
            if (lane >= off) wincl += n;
        }
        wsum[lane] = wincl - ws;                     // exclusive warp base
    }
    __syncthreads();

    const int base = wsum[wid] + (incl - s);         // exclusive prefix at pair
    g_off[2 * tid]     = base;
    g_off[2 * tid + 1] = base + a;
    g_cur[2 * tid]     = base;
    g_cur[2 * tid + 1] = base + a;
    if (tid == 1023) g_off[NROWS] = base + s;        // = NTOK
}

// ---------------------------------------------------------------------------
// K3: scatter token ids into row-grouped order
// ---------------------------------------------------------------------------
__global__ __launch_bounds__(256)
void scatter_kernel(const int* __restrict__ x)
{
    const int i = blockIdx.x * 256 + threadIdx.x;
    if (i < NTOK) {
        const int pos = atomicAdd(&g_cur[x[i]], 1);
        g_order[pos] = i;
    }
}

// ---------------------------------------------------------------------------
// K4: fused output kernel.
//  Blocks [0, NROWS): fast path. Load row once, stream to flag==0 destinations.
//  Blocks [NROWS, NROWS+SLOWG): slow path. Grid-stride all tokens, handle
//     flag != 0:  out[t] = e[x[t]] + sum_j w_j(t) * e[x[t-j]]
// ---------------------------------------------------------------------------
__global__ __launch_bounds__(512)
void main_kernel(const int* __restrict__ x,
                 const float* __restrict__ emb,
                 float* __restrict__ out)
{
    const int tid = threadIdx.x;

    if (blockIdx.x < NROWS) {
        const int r  = blockIdx.x;
        const int lo = g_off[r];
        const int hi = g_off[r + 1];
        if (lo == hi) return;

        __shared__ int      socc[64];
        __shared__ unsigned sfl[64];

        const float4 e = *reinterpret_cast<const float4*>(
            emb + (size_t)r * D + tid * 4);

        for (int base = lo; base < hi; base += 64) {
            const int n = min(64, hi - base);
            if (tid < n) {
                const int idx = g_order[base + tid];
                socc[tid] = idx;
                sfl[tid]  = g_flag[idx];
            }
            __syncthreads();
            for (int k = 0; k < n; k++) {
                if (sfl[k] == 0) {
                    __stcs(reinterpret_cast<float4*>(
                        out + (size_t)socc[k] * D + tid * 4), e);
                }
            }
            __syncthreads();
        }
    } else {
        // slow path: process every token whose flag != 0
        for (int tf = (int)blockIdx.x - NROWS; tf < NTOK; tf += SLOWG) {
            const unsigned m = g_flag[tf];
            if (m == 0) continue;

            float4 c = *reinterpret_cast<const float4*>(
                emb + (size_t)x[tf] * D + tid * 4);
#pragma unroll
            for (int j = 1; j <= HALO; j++) {
                if ((m >> j) & 1u) {
                    // bit j set => w_j != 0 => t-j >= 0 (boundary p's are zero)
                    const float  w = g_w[(size_t)tf * HALO + (j - 1)];
                    const float4 h = *reinterpret_cast<const float4*>(
                        emb + (size_t)x[tf - j] * D + tid * 4);
                    c.x = fmaf(h.x, w, c.x);
                    c.y = fmaf(h.y, w, c.y);
                    c.z = fmaf(h.z, w, c.z);
                    c.w = fmaf(h.w, w, c.w);
                }
            }
            __stcs(reinterpret_cast<float4*>(
                out + (size_t)tf * D + tid * 4), c);
        }
    }
}

extern "C" void kernel_launch(void* const* d_in, const int* in_sizes, int n_in,
                              void* d_out, int out_size)
{
    const int*   x   = (const int*)d_in[0];
    const float* emb = (const float*)d_in[1];
    float*       out = (float*)d_out;

    dim3 gridW(S / TTW, B);                  // 64 x 4
    weights_kernel<<<gridW, 128>>>(x);
    histprefix_kernel<<<1, 1024>>>(x);
    scatter_kernel<<<NTOK / 256, 256>>>(x);
    main_kernel<<<NROWS + SLOWG, 512>>>(x, emb, out);
}

// round 12
// speedup vs baseline: 1.2222x; 1.2222x over previous
#include <cuda_runtime.h>
#include <cuda_bf16.h>
#include <cstdint>

// Problem shapes (fixed for this dataset entry)
constexpr int B = 4;
constexpr int S = 4096;
constexpr int D = 2048;
constexpr int HALO  = 8;        // recurrence depth N_BLANKS
constexpr int NROWS = 2048;     // x values span [0, 2048)
constexpr int NTOK  = B * S;    // 16384 tokens
constexpr int TTW   = 64;       // weights-kernel t-tile
constexpr int CHUNK = 16;       // tokens per output block
constexpr int NCHUNK = NTOK / CHUNK;  // 1024 output blocks

// Device scratch (no allocs allowed)
__device__ float    g_w[NTOK * HALO];     // w_1..w_8 per token
__device__ unsigned g_flag[NTOK];         // nonzero-weight mask per token
__device__ int      g_off[NROWS + 1];     // row start offsets
__device__ int      g_cur[NROWS];         // scatter cursors
__device__ int      g_order[NTOK];        // token ids grouped by row

// ---------------------------------------------------------------------------
// K1: weight DP per t-tile.
//   w^k[t][j] = w^{k-1}[t][j] + p[t-k] * w^{k-1}[t-1][j-1],  w_0 == 1 implicit
//   p[t] = (x[t] >= 16) && (x[t+1] < 16), zero outside [0, S-1)
// ---------------------------------------------------------------------------
__global__ __launch_bounds__(128)
void weights_kernel(const int* __restrict__ x)
{
    const int b   = blockIdx.y;
    const int T0  = blockIdx.x * TTW;
    const int tid = threadIdx.x;

    __shared__ float sp[TTW + 2 * HALO];             // p[t], t = T0-2*HALO+i
    __shared__ float wbuf[2][TTW + HALO][HALO];

    for (int i = tid; i < TTW + 2 * HALO; i += 128) {
        int t = T0 - 2 * HALO + i;
        float pv = 0.0f;
        if (t >= 0 && t + 1 < S) {
            int xt  = x[b * S + t];
            int xt1 = x[b * S + t + 1];
            pv = (xt1 < 16 && xt >= 16) ? 1.0f : 0.0f;
        }
        sp[i] = pv;
    }
    float wloc[HALO];
#pragma unroll
    for (int j = 0; j < HALO; j++) wloc[j] = 0.0f;
    if (tid < TTW + HALO) {
#pragma unroll
        for (int j = 0; j < HALO; j++) wbuf[0][tid][j] = 0.0f;
    }
    __syncthreads();

    for (int k = 1; k <= HALO; k++) {
        const int cur = k & 1, prv = cur ^ 1;
        if (tid < TTW + HALO) {
            float nb[HALO - 1];
            float nb0 = 0.0f;
            if (tid > 0) {
                nb0 = 1.0f;
#pragma unroll
                for (int j = 0; j < HALO - 1; j++) nb[j] = wbuf[prv][tid - 1][j];
            } else {
#pragma unroll
                for (int j = 0; j < HALO - 1; j++) nb[j] = 0.0f;
            }
            const float pv = sp[tid + HALO - k];
            wloc[0] = fmaf(pv, nb0, wloc[0]);
#pragma unroll
            for (int j = 1; j < HALO; j++) wloc[j] = fmaf(pv, nb[j - 1], wloc[j]);
#pragma unroll
            for (int j = 0; j < HALO; j++) wbuf[cur][tid][j] = wloc[j];
        }
        __syncthreads();
    }

    if (tid >= HALO && tid < TTW + HALO) {
        const int t  = T0 - HALO + tid;              // in [T0, T0+TTW)
        const int tf = b * S + t;
        unsigned m = 0;
#pragma unroll
        for (int j = 0; j < HALO; j++) {
            if (wloc[j] != 0.0f) m |= (1u << (j + 1));
            g_w[(size_t)tf * HALO + j] = wloc[j];
        }
        g_flag[tf] = m;
    }
}

// ---------------------------------------------------------------------------
// K2: single-block histogram + exclusive scan -> g_off, g_cur
// ---------------------------------------------------------------------------
__global__ __launch_bounds__(1024)
void histprefix_kernel(const int* __restrict__ x)
{
    __shared__ int hist[NROWS];
    __shared__ int wsum[32];
    const int tid  = threadIdx.x;
    const int lane = tid & 31;
    const int wid  = tid >> 5;

    hist[tid] = 0;
    hist[tid + 1024] = 0;
    __syncthreads();

    for (int i = tid; i < NTOK; i += 1024)
        atomicAdd(&hist[x[i]], 1);
    __syncthreads();

    // scan of 2048 counts, 2 per thread
    const int a  = hist[2 * tid];
    const int bb = hist[2 * tid + 1];
    const int s  = a + bb;

    int incl = s;                                    // warp inclusive scan of s
#pragma unroll
    for (int off = 1; off < 32; off <<= 1) {
        const int n = __shfl_up_sync(0xFFFFFFFFu, incl, off);
        if (lane >= off) incl += n;
    }
    if (lane == 31) wsum[wid] = incl;
    __syncthreads();
    if (wid == 0) {
        const int ws = wsum[lane];
        int wincl = ws;
#pragma unroll
        for (int off = 1; off < 32; off <<= 1) {
            const int n = __shfl_up_sync(0xFFFFFFFFu, wincl, off);
            if (lane >= off) wincl += n;
        }
        wsum[lane] = wincl - ws;                     // exclusive warp base
    }
    __syncthreads();

    const int base = wsum[wid] + (incl - s);         // exclusive prefix at pair
    g_off[2 * tid]     = base;
    g_off[2 * tid + 1] = base + a;
    g_cur[2 * tid]     = base;
    g_cur[2 * tid + 1] = base + a;
    if (tid == 1023) g_off[NROWS] = base + s;        // = NTOK
}

// ---------------------------------------------------------------------------
// K3: scatter token ids into row-grouped order
// ---------------------------------------------------------------------------
__global__ __launch_bounds__(256)
void scatter_kernel(const int* __restrict__ x)
{
    const int i = blockIdx.x * 256 + threadIdx.x;
    if (i < NTOK) {
        const int pos = atomicAdd(&g_cur[x[i]], 1);
        g_order[pos] = i;
    }
}

// ---------------------------------------------------------------------------
// K4: balanced chunked output.
//  Block = 16 consecutive g_order entries (row-grouped => ~2-3 distinct rows).
//  Row held in registers (1 float4/thread), reloaded only on row change
//  (block-uniform branch). Slow tokens (flag != 0) corrected inline:
//     out[t] = e[x[t]] + sum_j w_j(t) * e[x[t-j]]
//  Correctness does not depend on g_order's ordering; grouping is a perf hint.
// ---------------------------------------------------------------------------
__global__ __launch_bounds__(512)
void out_kernel(const int* __restrict__ x,
                const float* __restrict__ emb,
                float* __restrict__ out)
{
    const int tid = threadIdx.x;
    const int c0  = blockIdx.x * CHUNK;

    __shared__ int      socc[CHUNK];
    __shared__ int      srow[CHUNK];
    __shared__ unsigned sfl[CHUNK];

    if (tid < CHUNK) {
        const int idx = g_order[c0 + tid];
        socc[tid] = idx;
        srow[tid] = __ldg(&x[idx]);
        sfl[tid]  = g_flag[idx];
    }
    __syncthreads();

    float4 e = make_float4(0.f, 0.f, 0.f, 0.f);
    int cur = -1;

    for (int k = 0; k < CHUNK; k++) {
        const int r = srow[k];                       // block-uniform
        if (r != cur) {
            e = *reinterpret_cast<const float4*>(emb + (size_t)r * D + tid * 4);
            cur = r;
        }
        float4 c = e;
        const unsigned m = sfl[k];
        if (m) {
            const int tf = socc[k];
#pragma unroll
            for (int j = 1; j <= HALO; j++) {
                if ((m >> j) & 1u) {
                    // bit j set => w_j != 0 => tf-j stays inside this sequence
                    const float w   = __ldg(&g_w[(size_t)tf * HALO + (j - 1)]);
                    const int   rj  = __ldg(&x[tf - j]);
                    const float4 h  = *reinterpret_cast<const float4*>(
                        emb + (size_t)rj * D + tid * 4);
                    c.x = fmaf(h.x, w, c.x);
                    c.y = fmaf(h.y, w, c.y);
                    c.z = fmaf(h.z, w, c.z);
                    c.w = fmaf(h.w, w, c.w);
                }
            }
        }
        __stcs(reinterpret_cast<float4*>(out + (size_t)socc[k] * D + tid * 4), c);
    }
}

extern "C" void kernel_launch(void* const* d_in, const int* in_sizes, int n_in,
                              void* d_out, int out_size)
{
    const int*   x   = (const int*)d_in[0];
    const float* emb = (const float*)d_in[1];
    float*       out = (float*)d_out;

    dim3 gridW(S / TTW, B);                  // 64 x 4
    weights_kernel<<<gridW, 128>>>(x);
    histprefix_kernel<<<1, 1024>>>(x);
    scatter_kernel<<<NTOK / 256, 256>>>(x);
    out_kernel<<<NCHUNK, 512>>>(x, emb, out);
}